// round 1
// baseline (speedup 1.0000x reference)
#include <cuda_runtime.h>
#include <cuda_bf16.h>

// CTC loss forward: T=1000, B=32, C=1000, S=100, blank=0, zero_infinity, sum over batch.
// One CTA per batch element; one thread per trellis position (L=2S+1=201);
// alpha double-buffered in shared memory; log2-domain lse3; 8-deep register
// prefetch ring for the emit gathers.

#define TT 1000
#define BB 32
#define CC 1000
#define SS 100
#define LL (2 * SS + 1)      // 201
#define NTHREADS 224         // 7 warps, covers LL positions
#define PF 8                 // prefetch pipeline depth (steps of lead)

#define NEGF (-1e30f)
#define LOG2E_F 1.4426950408889634f
#define LN2_F 0.6931471805599453f

__device__ float g_loss[BB];

__global__ void __launch_bounds__(NTHREADS, 1)
ctc_alpha_kernel(const float* __restrict__ logp,
                 const int* __restrict__ targets,
                 const int* __restrict__ input_lens,
                 const int* __restrict__ target_lens) {
    __shared__ float sbuf[2][LL + 2];   // +2 front pad of NEG so l-1, l-2 are branch-free

    const int b = blockIdx.x;
    const int l = threadIdx.x;
    const bool active = (l < LL);

    const int il = input_lens[b];
    const int tl = target_lens[b];
    const int Lv = 2 * tl + 1;          // number of valid trellis columns
    const bool validl = active && (l < Lv);

    // Extended label for this position and skip-transition permission.
    int lbl = 0;                        // blank
    bool skip = false;
    if (active && (l & 1)) {
        int s = (l - 1) >> 1;
        lbl = targets[b * SS + s];
        skip = (s > 0) && (lbl != 0) && (lbl != targets[b * SS + s - 1]);
    }

    // Front pad (positions -2, -1) is permanent NEG in both buffers.
    if (l < 2) { sbuf[0][l] = NEGF; sbuf[1][l] = NEGF; }

    // Per-thread gather column: logp[t, b, lbl], stride BB*CC floats per t.
    const float* gptr = logp + (long)b * CC + lbl;

    // Prime the prefetch ring with t = 0..PF-1.
    float pf[PF];
#pragma unroll
    for (int j = 0; j < PF; j++)
        pf[j] = (active && j < TT) ? gptr[(long)j * BB * CC] : 0.0f;

    // ---- t = 0 ----
    {
        float e2 = pf[0] * LOG2E_F;
        float a0 = (validl && l <= 1) ? e2 : NEGF;
        if (active) sbuf[0][l + 2] = a0;
        // refill slot 0 with t = PF
        if (active && PF < TT) pf[0] = gptr[(long)PF * BB * CC];
    }
    __syncthreads();
    int p = 0;

    if (il == 1 && l == 0) {
        float lb = sbuf[p][2 * tl + 2];
        float lw = sbuf[p][2 * tl + 1];
        float mm = fmaxf(lb, lw);
        float loss = -(mm + log2f(exp2f(lb - mm) + exp2f(lw - mm))) * LN2_F;
        if (loss > 0.5e30f) loss = 0.0f;
        g_loss[b] = loss;
    }

    // ---- t = 1 .. TT-1 ----
#pragma unroll 1
    for (int t0 = 1; t0 < TT; t0 += PF) {
#pragma unroll
        for (int j = 0; j < PF; j++) {
            int t = t0 + j;
            if (t >= TT) break;
            int slot = t & (PF - 1);
            float e = pf[slot];
            int tn = t + PF;
            if (active && tn < TT) pf[slot] = gptr[(long)tn * BB * CC];

            if (active) {
                float e2 = e * LOG2E_F;
                float a  = sbuf[p][l + 2];
                float a1 = sbuf[p][l + 1];
                float a2 = skip ? sbuf[p][l] : NEGF;
                float m  = fmaxf(a, fmaxf(a1, a2));
                float ss = exp2f(a - m) + exp2f(a1 - m) + exp2f(a2 - m);
                float nv = m + log2f(ss) + e2;
                sbuf[p ^ 1][l + 2] = validl ? nv : NEGF;
            }
            __syncthreads();
            p ^= 1;

            if (t == il - 1 && l == 0) {
                float lb = sbuf[p][2 * tl + 2];
                float lw = sbuf[p][2 * tl + 1];
                float mm = fmaxf(lb, lw);
                float loss = -(mm + log2f(exp2f(lb - mm) + exp2f(lw - mm))) * LN2_F;
                if (loss > 0.5e30f) loss = 0.0f;
                g_loss[b] = loss;
            }
        }
    }
}

__global__ void ctc_reduce_kernel(float* __restrict__ out) {
    if (threadIdx.x == 0) {
        float s = 0.0f;
        for (int i = 0; i < BB; i++) s += g_loss[i];
        out[0] = s;
    }
}

extern "C" void kernel_launch(void* const* d_in, const int* in_sizes, int n_in,
                              void* d_out, int out_size) {
    const float* logp        = (const float*)d_in[0];
    const int*   targets     = (const int*)d_in[1];
    const int*   input_lens  = (const int*)d_in[2];
    const int*   target_lens = (const int*)d_in[3];
    float* out = (float*)d_out;

    ctc_alpha_kernel<<<BB, NTHREADS>>>(logp, targets, input_lens, target_lens);
    ctc_reduce_kernel<<<1, 32>>>(out);
}

// round 2
// speedup vs baseline: 1.0889x; 1.0889x over previous
#include <cuda_runtime.h>
#include <cuda_bf16.h>

// CTC loss forward: T=1000, B=32, C=1000, S=100, blank=0, zero_infinity, sum over batch.
// One CTA per batch element; one thread per trellis position (L=2S+1=201);
// alpha double-buffered in shared memory; log2-domain lse3 using MUFU
// ex2.approx/lg2.approx (single-instruction transcendentals); 8-deep register
// prefetch ring for the emit gathers.

#define TT 1000
#define BB 32
#define CC 1000
#define SS 100
#define LL (2 * SS + 1)      // 201
#define NTHREADS 224         // 7 warps, covers LL positions
#define PF 8                 // prefetch pipeline depth (steps of lead)

#define NEGF (-1e30f)
#define LOG2E_F 1.4426950408889634f
#define LN2_F 0.6931471805599453f

__device__ float g_loss[BB];

__device__ __forceinline__ float fast_ex2(float x) {
    float y;
    asm("ex2.approx.ftz.f32 %0, %1;" : "=f"(y) : "f"(x));
    return y;
}
__device__ __forceinline__ float fast_lg2(float x) {
    float y;
    asm("lg2.approx.f32 %0, %1;" : "=f"(y) : "f"(x));
    return y;
}

__global__ void __launch_bounds__(NTHREADS, 1)
ctc_alpha_kernel(const float* __restrict__ logp,
                 const int* __restrict__ targets,
                 const int* __restrict__ input_lens,
                 const int* __restrict__ target_lens) {
    __shared__ float sbuf[2][LL + 2];   // +2 front pad of NEG so l-1, l-2 are branch-free

    const int b = blockIdx.x;
    const int l = threadIdx.x;
    const bool active = (l < LL);

    const int il = input_lens[b];
    const int tl = target_lens[b];
    const int Lv = 2 * tl + 1;          // number of valid trellis columns
    const bool validl = active && (l < Lv);

    // Extended label for this position and skip-transition permission.
    int lbl = 0;                        // blank
    bool skip = false;
    if (active && (l & 1)) {
        int s = (l - 1) >> 1;
        lbl = targets[b * SS + s];
        skip = (s > 0) && (lbl != 0) && (lbl != targets[b * SS + s - 1]);
    }

    // Front pad (positions -2, -1) is permanent NEG in both buffers.
    if (l < 2) { sbuf[0][l] = NEGF; sbuf[1][l] = NEGF; }

    // Per-thread gather column: logp[t, b, lbl], stride BB*CC floats per t.
    const float* gptr = logp + (long)b * CC + lbl;

    // Prime the prefetch ring with t = 0..PF-1.
    float pf[PF];
#pragma unroll
    for (int j = 0; j < PF; j++)
        pf[j] = (active && j < TT) ? gptr[(long)j * BB * CC] : 0.0f;

    // ---- t = 0 ----
    {
        float e2 = pf[0] * LOG2E_F;
        float a0 = (validl && l <= 1) ? e2 : NEGF;
        if (active) sbuf[0][l + 2] = a0;
        // refill slot 0 with t = PF
        if (active && PF < TT) pf[0] = gptr[(long)PF * BB * CC];
    }
    __syncthreads();
    int p = 0;

    if (il == 1 && l == 0) {
        float lb = sbuf[p][2 * tl + 2];
        float lw = sbuf[p][2 * tl + 1];
        float mm = fmaxf(lb, lw);
        float loss = -(mm + fast_lg2(fast_ex2(lb - mm) + fast_ex2(lw - mm))) * LN2_F;
        if (loss > 0.5e30f) loss = 0.0f;
        g_loss[b] = loss;
    }

    // ---- t = 1 .. TT-1 ----
#pragma unroll 1
    for (int t0 = 1; t0 < TT; t0 += PF) {
#pragma unroll
        for (int j = 0; j < PF; j++) {
            int t = t0 + j;
            if (t >= TT) break;
            int slot = t & (PF - 1);
            float e = pf[slot];
            int tn = t + PF;
            if (active && tn < TT) pf[slot] = gptr[(long)tn * BB * CC];

            if (active) {
                float e2 = e * LOG2E_F;
                float a  = sbuf[p][l + 2];
                float a1 = sbuf[p][l + 1];
                float a2 = skip ? sbuf[p][l] : NEGF;
                float m  = fmaxf(a, fmaxf(a1, a2));
                float ss = fast_ex2(a - m) + fast_ex2(a1 - m) + fast_ex2(a2 - m);
                float nv = m + fast_lg2(ss) + e2;
                sbuf[p ^ 1][l + 2] = validl ? nv : NEGF;
            }
            __syncthreads();
            p ^= 1;

            if (t == il - 1 && l == 0) {
                float lb = sbuf[p][2 * tl + 2];
                float lw = sbuf[p][2 * tl + 1];
                float mm = fmaxf(lb, lw);
                float loss = -(mm + fast_lg2(fast_ex2(lb - mm) + fast_ex2(lw - mm))) * LN2_F;
                if (loss > 0.5e30f) loss = 0.0f;
                g_loss[b] = loss;
            }
        }
    }
}

__global__ void ctc_reduce_kernel(float* __restrict__ out) {
    if (threadIdx.x == 0) {
        float s = 0.0f;
        for (int i = 0; i < BB; i++) s += g_loss[i];
        out[0] = s;
    }
}

extern "C" void kernel_launch(void* const* d_in, const int* in_sizes, int n_in,
                              void* d_out, int out_size) {
    const float* logp        = (const float*)d_in[0];
    const int*   targets     = (const int*)d_in[1];
    const int*   input_lens  = (const int*)d_in[2];
    const int*   target_lens = (const int*)d_in[3];
    float* out = (float*)d_out;

    ctc_alpha_kernel<<<BB, NTHREADS>>>(logp, targets, input_lens, target_lens);
    ctc_reduce_kernel<<<1, 32>>>(out);
}

// round 4
// speedup vs baseline: 5.7417x; 5.2729x over previous
#include <cuda_runtime.h>
#include <cuda_bf16.h>
#include <cstdint>

// CTC loss forward, linear-prob domain with PER-LANE block-floating-point.
// prep: compact+exp emit table E[b][t][256] (per-thread layout, valid-masked).
// hot:  1 warp per batch, alpha mantissas in registers (7 pos/lane) + per-lane
//       int exponent renormalized every step; neighbors via shfl with exact
//       power-of-2 rebasing; emit rows streamed via cp.async.bulk 3-slot ring.

#define TT 1000
#define BB 32
#define CC 1000
#define SS 100
#define LL 201          // 2*SS+1
#define TPAD 1024
#define ESLOT 256       // floats per (t,b): 32 lanes x 8 (7 used + 1 pad)
#define CH 15           // rows per ring slot
#define NSLOT 3
#define LOG2E_F 1.4426950408889634f
#define LN2_F 0.6931471805599453f
#define EDEAD (-(1 << 28))

__device__ float g_E[BB][TPAD][ESLOT];   // ~33.5 MB static scratch
__device__ float g_state[BB][ESLOT];
__device__ int   g_estate[BB][32];
__device__ float g_loss[BB];

__device__ __forceinline__ float fast_ex2(float x) {
    float y; asm("ex2.approx.ftz.f32 %0, %1;" : "=f"(y) : "f"(x)); return y;
}
__device__ __forceinline__ float fast_lg2(float x) {
    float y; asm("lg2.approx.f32 %0, %1;" : "=f"(y) : "f"(x)); return y;
}
__device__ __forceinline__ uint32_t s2u(const void* p) {
    return (uint32_t)__cvta_generic_to_shared(p);
}
__device__ __forceinline__ void mbar_init(uint32_t mb, uint32_t cnt) {
    asm volatile("mbarrier.init.shared.b64 [%0], %1;" :: "r"(mb), "r"(cnt) : "memory");
}
__device__ __forceinline__ void mbar_wait(uint32_t mb, uint32_t parity) {
    asm volatile(
        "{\n\t.reg .pred P;\n\t"
        "WL%=:\n\t"
        "mbarrier.try_wait.parity.acquire.cta.shared::cta.b64 P, [%0], %1, 0x989680;\n\t"
        "@P bra WD%=;\n\t"
        "bra WL%=;\n\t"
        "WD%=:\n\t}"
        :: "r"(mb), "r"(parity) : "memory");
}
// exact 2^d for d <= 0 (flushes to 0 below 2^-127)
__device__ __forceinline__ float pow2_clamped(int d) {
    int u = 127 + d; if (u < 0) u = 0;
    return __uint_as_float((unsigned)u << 23);
}

// ---------------- prep: E[b][t][k*8+j] = exp2(logp[t,b,ext(7k+j)]*log2e) -----
__global__ void ctc_prep(const float* __restrict__ logp,
                         const int* __restrict__ targets,
                         const int* __restrict__ target_lens) {
    int t = blockIdx.x, b = blockIdx.y, i = threadIdx.x;
    int k = i >> 3, j = i & 7;
    int l = 7 * k + j;
    int Lv = 2 * target_lens[b] + 1;
    float val = 0.0f;
    if (j < 7 && l < Lv) {
        int lbl = (l & 1) ? targets[b * SS + ((l - 1) >> 1)] : 0;
        float lp = logp[((long)t * BB + b) * CC + lbl];
        val = fast_ex2(lp * LOG2E_F);
    }
    g_E[b][t][i] = val;
}

// final-loss emit: alpha at end positions, (mantissa, exponent) pair-reduce
__device__ __forceinline__ void emit_loss(int b, const float a[7], int E,
                                          int lane, int end1, int end2) {
    float c = 0.0f;
#pragma unroll
    for (int j = 0; j < 7; j++) {
        int l = 7 * lane + j;
        if (l == end1 || l == end2) c += a[j];
    }
    int Ec = (c > 0.0f) ? E : EDEAD;
#pragma unroll
    for (int o = 16; o > 0; o >>= 1) {
        float co = __shfl_xor_sync(~0u, c, o);
        int   Eo = __shfl_xor_sync(~0u, Ec, o);
        int   Em = (Ec > Eo) ? Ec : Eo;
        c = c * pow2_clamped(Ec - Em) + co * pow2_clamped(Eo - Em);
        Ec = Em;
    }
    if (lane == 0) {
        float lv = -(fast_lg2(c) + (float)Ec) * LN2_F;
        if (!(lv <= 0.5e30f)) lv = 0.0f;   // zero_infinity (inf/nan)
        g_loss[b] = lv;
    }
}

// ---------------- hot chunk: advance alpha over [t_begin, t_end) -------------
__global__ void __launch_bounds__(32, 1)
ctc_chunk(const int* __restrict__ targets,
          const int* __restrict__ input_lens,
          const int* __restrict__ target_lens,
          int t_begin, int t_end) {
    __shared__ __align__(16) float se[NSLOT * CH * ESLOT];
    __shared__ __align__(8) uint64_t mbar[NSLOT];

    const int b = blockIdx.x;
    const int lane = threadIdx.x;
    const uint32_t se_base = s2u(se);
    const uint32_t mb_base = s2u(mbar);

    const int il_m1 = input_lens[b] - 1;
    const int tl = target_lens[b];
    const int end1 = 2 * tl;
    const int end2 = 2 * tl - 1;

    // skip-transition multipliers (compile-time-fixed per lane)
    float s[7];
#pragma unroll
    for (int j = 0; j < 7; j++) {
        int l = 7 * lane + j;
        float sv = 0.0f;
        if ((l & 1) && l < LL) {
            int si = (l - 1) >> 1;
            if (si > 0) {
            int c0 = targets[b * SS + si];
            int c1 = targets[b * SS + si - 1];
            sv = (c0 != 0 && c0 != c1) ? 1.0f : 0.0f;
            }
        }
        s[j] = sv;
    }

    float a[7];
    int E;
    if (t_begin == 0) {
#pragma unroll
        for (int j = 0; j < 7; j++) {
            int l = 7 * lane + j;
            a[j] = (l <= 1) ? g_E[b][0][lane * 8 + j] : 0.0f;
        }
        E = 0;
        if (il_m1 == 0) emit_loss(b, a, E, lane, end1, end2);
    } else {
#pragma unroll
        for (int j = 0; j < 7; j++) a[j] = g_state[b][lane * 8 + j];
        E = g_estate[b][lane];
    }

    // ---- emit-row pipeline ----
    const int cbase = (t_begin == 0) ? 1 : t_begin;
    const int nrows = t_end - cbase;
    const int nchunks = (nrows + CH - 1) / CH;

    if (lane == 0) {
#pragma unroll
        for (int q = 0; q < NSLOT; q++) mbar_init(mb_base + q * 8, 1);
        asm volatile("fence.proxy.async.shared::cta;" ::: "memory");
    }
    __syncwarp();

#pragma unroll
    for (int q = 0; q < NSLOT; q++) {
        if (lane == 0 && q < nchunks) {
            uint32_t mb = mb_base + (q % NSLOT) * 8;
            asm volatile("mbarrier.arrive.expect_tx.shared.b64 _, [%0], %1;"
                         :: "r"(mb), "r"(CH * ESLOT * 4) : "memory");
            uint32_t dst = se_base + (q % NSLOT) * (CH * ESLOT * 4);
            const float* src = &g_E[b][cbase + q * CH][0];
            asm volatile("cp.async.bulk.shared::cta.global.mbarrier::complete_tx::bytes "
                         "[%0], [%1], %2, [%3];"
                         :: "r"(dst), "l"(src), "r"(CH * ESLOT * 4), "r"(mb) : "memory");
        }
    }

    int t = cbase;
    for (int c = 0; c < nchunks; c++) {
        mbar_wait(mb_base + (c % NSLOT) * 8, (uint32_t)((c / NSLOT) & 1));
        int q = c + 2;
        if (c >= 1 && lane == 0 && q < nchunks) {
            uint32_t mb = mb_base + (q % NSLOT) * 8;
            asm volatile("mbarrier.arrive.expect_tx.shared.b64 _, [%0], %1;"
                         :: "r"(mb), "r"(CH * ESLOT * 4) : "memory");
            uint32_t dst = se_base + (q % NSLOT) * (CH * ESLOT * 4);
            const float* src = &g_E[b][cbase + q * CH][0];
            asm volatile("cp.async.bulk.shared::cta.global.mbarrier::complete_tx::bytes "
                         "[%0], [%1], %2, [%3];"
                         :: "r"(dst), "l"(src), "r"(CH * ESLOT * 4), "r"(mb) : "memory");
        }

        int rmax = t_end - t; if (rmax > CH) rmax = CH;
        const float4* slotp = (const float4*)(se + (c % NSLOT) * (CH * ESLOT)) + lane * 2;
#pragma unroll 1
        for (int r = 0; r < rmax; r++, t++) {
            float4 e0 = slotp[r * (ESLOT / 4)];
            float4 e1 = slotp[r * (ESLOT / 4) + 1];

            // neighbor terms from previous lane, with exponent rebasing
            float p6 = __shfl_up_sync(~0u, a[6], 1);
            float p5 = __shfl_up_sync(~0u, a[5], 1);
            int   Ep = __shfl_up_sync(~0u, E, 1);
            if (lane == 0) { p5 = 0.0f; p6 = 0.0f; }   // Ep==E then, d=0 harmless

            int Em = (E > Ep) ? E : Ep;
            float sa = pow2_clamped(E - Em);
            float sp = pow2_clamped(Ep - Em);
            p6 *= sp; p5 *= sp;
#pragma unroll
            for (int j = 0; j < 7; j++) a[j] *= sa;

            float n0 = fmaf(s[0], p5, a[0] + p6) * e0.x;
            float n1 = fmaf(s[1], p6, a[1] + a[0]) * e0.y;
            float n2 = fmaf(s[2], a[0], a[2] + a[1]) * e0.z;
            float n3 = fmaf(s[3], a[1], a[3] + a[2]) * e0.w;
            float n4 = fmaf(s[4], a[2], a[4] + a[3]) * e1.x;
            float n5 = fmaf(s[5], a[3], a[5] + a[4]) * e1.y;
            float n6 = fmaf(s[6], a[4], a[6] + a[5]) * e1.z;

            // per-lane renorm: bring lane max back to ~[1,2)
            float m = fmaxf(fmaxf(fmaxf(n0, n1), fmaxf(n2, n3)),
                            fmaxf(fmaxf(n4, n5), n6));
            unsigned u = __float_as_uint(m) >> 23;      // m >= 0, so exponent bits
            int shift = 127 - (int)u;                   // target exponent 0
            if (shift > 127) shift = 127;               // dead lane (m==0) clamp
            float f = __uint_as_float((unsigned)(shift + 127) << 23);
            E = Em - shift;
            a[0] = n0 * f; a[1] = n1 * f; a[2] = n2 * f; a[3] = n3 * f;
            a[4] = n4 * f; a[5] = n5 * f; a[6] = n6 * f;

            if (t == il_m1) emit_loss(b, a, E, lane, end1, end2);
        }
    }

#pragma unroll
    for (int j = 0; j < 7; j++) g_state[b][lane * 8 + j] = a[j];
    g_estate[b][lane] = E;
}

__global__ void ctc_reduce_kernel(float* __restrict__ out) {
    if (threadIdx.x == 0) {
        float sum = 0.0f;
        for (int i = 0; i < BB; i++) sum += g_loss[i];
        out[0] = sum;
    }
}

extern "C" void kernel_launch(void* const* d_in, const int* in_sizes, int n_in,
                              void* d_out, int out_size) {
    const float* logp        = (const float*)d_in[0];
    const int*   targets     = (const int*)d_in[1];
    const int*   input_lens  = (const int*)d_in[2];
    const int*   target_lens = (const int*)d_in[3];
    float* out = (float*)d_out;

    dim3 pgrid(TT, BB);
    ctc_prep<<<pgrid, 256>>>(logp, targets, target_lens);
    ctc_chunk<<<BB, 32>>>(targets, input_lens, target_lens, 0, TT / 2);
    ctc_chunk<<<BB, 32>>>(targets, input_lens, target_lens, TT / 2, TT);
    ctc_reduce_kernel<<<1, 32>>>(out);
}